// round 7
// baseline (speedup 1.0000x reference)
#include <cuda_runtime.h>
#include <cstdint>

// ---------------------------------------------------------------------------
// Problem constants
// ---------------------------------------------------------------------------
#define BB 4
#define HH 224
#define WW 224
#define HW (HH * WW)                 // 50176
#define NPLANE 128                   // B*C
#define NTOT ((size_t)NPLANE * HW)   // 6,422,528 floats

#define ST 4                     // steps per pipeline stage
#define NS 3                     // pipeline stages
#define NGRP (HH / ST)           // 56 groups
#define ABYTES (ST * 224 * 4)    // bytes per array within a stage = 3584
#define STAGEB (4 * ABYTES)      // stage bytes = 14336
#define XB_OFF (NS * STAGEB)     // xchg buffer offset = 43008
#define SMEM_BYTES (XB_OFF + 64 + 512)  // stages + xchg + overflow pad

// Scratch (no cudaMalloc allowed)
__device__ __align__(256) float g_x[NTOT];
__device__ __align__(256) float g_dir[4 * NTOT];

// ---------------------------------------------------------------------------
// cp.async helpers
// ---------------------------------------------------------------------------
__device__ __forceinline__ uint32_t s2u(const void* p) {
    return (uint32_t)__cvta_generic_to_shared(p);
}
__device__ __forceinline__ void cpa16(uint32_t dst, const float* src) {
    asm volatile("cp.async.cg.shared.global [%0], [%1], 16;" ::"r"(dst),
                 "l"(src));
}
__device__ __forceinline__ void cpa_commit() {
    asm volatile("cp.async.commit_group;");
}
__device__ __forceinline__ void cpa_waitN() {
    asm volatile("cp.async.wait_group %0;" ::"n"(NS - 1));
}

// 128B-line chunk swizzle (16B granularity) for the horizontal layout.
__device__ __forceinline__ uint32_t swz(uint32_t byte_off) {
    return byte_off ^ ((byte_off >> 3) & 0x70);
}

// ---------------------------------------------------------------------------
// K0: conv2d 3x3 same, 2 -> 32, writes g_x
// ---------------------------------------------------------------------------
__global__ void conv_in_kernel(const float* __restrict__ y,
                               const float* __restrict__ w3) {
    __shared__ float ws[576];
    for (int i = threadIdx.x; i < 576; i += blockDim.x) ws[i] = w3[i];
    __syncthreads();

    int idx = blockIdx.x * blockDim.x + threadIdx.x;
    if (idx >= BB * HW) return;
    int b = idx / HW, pix = idx - b * HW;
    int py = pix / WW, px = pix - py * WW;

    float in[2][3][3];
#pragma unroll
    for (int ic = 0; ic < 2; ic++)
#pragma unroll
        for (int ky = 0; ky < 3; ky++)
#pragma unroll
            for (int kx = 0; kx < 3; kx++) {
                int yy = py + ky - 1, xx = px + kx - 1;
                bool v = ((unsigned)yy < HH) && ((unsigned)xx < WW);
                in[ic][ky][kx] =
                    v ? __ldg(y + ((size_t)(b * 2 + ic)) * HW + yy * WW + xx)
                      : 0.0f;
            }

    for (int oc = 0; oc < 32; oc++) {
        float a = 0.0f;
#pragma unroll
        for (int ic = 0; ic < 2; ic++)
#pragma unroll
            for (int k = 0; k < 9; k++)
                a += in[ic][k / 3][k % 3] * ws[(oc * 2 + ic) * 9 + k];
        g_x[((size_t)(b * 32 + oc)) * HW + pix] = a;
    }
}

// ---------------------------------------------------------------------------
// 2-warp cooperative scan with halo overlap.
//   Warp0: threads 0..29 hold lanes s0=4*tid  (own 0..111, halo 112..119)
//   Warp1: threads 0..29 hold lanes s0=104+4*tid (halo 104..111, own 112..223)
//   Halo refreshed from the other warp's owned values every ST=4 steps via an
//   8-float smem exchange; owned lanes remain bit-exact (error front moves
//   1 lane/step and never crosses the 8-lane halo within a group).
//   All stage consumption is LDS.128; vertical stores STG.128; horizontal
//   outputs buffered 4 steps -> STG.128.
// ---------------------------------------------------------------------------
template <bool HOR, bool REV>
__device__ void warp_scan2(const float* __restrict__ g1,
                           const float* __restrict__ g2,
                           const float* __restrict__ g3,
                           const float* __restrict__ xp,
                           float* __restrict__ yp, char* sb, float* xb, int w,
                           int tid) {
    const float* arr[4] = {g1, g2, g3, xp};
    const int a0 = 2 * w;  // each warp fills 2 of the 4 arrays
    uint32_t su = s2u(sb);

    auto fill = [&](int st, int tg) {
        uint32_t stb = su + (uint32_t)(st * STAGEB);
        if (HOR) {
            int base = REV ? 220 - 4 * tg : 4 * tg;
#pragma unroll
            for (int ai = 0; ai < 2; ai++) {
                int a = a0 + ai;
                const float* src = arr[a] + base;
#pragma unroll
                for (int k = 0; k < 7; k++) {
                    int s = tid + 32 * k;
                    cpa16(stb + swz((uint32_t)(a * ABYTES + s * 16)),
                          src + (size_t)s * WW);
                }
            }
        } else {
#pragma unroll
            for (int ai = 0; ai < 2; ai++) {
                int a = a0 + ai;
#pragma unroll
                for (int j = 0; j < 4; j++) {
                    int row = REV ? 223 - (4 * tg + j) : 4 * tg + j;
                    const float* src = arr[a] + (size_t)row * WW;
                    uint32_t dst = stb + (uint32_t)(a * ABYTES + j * 896);
                    cpa16(dst + tid * 16, src + tid * 4);
                    if (tid < 24)
                        cpa16(dst + (32 + tid) * 16, src + (32 + tid) * 4);
                }
            }
        }
        cpa_commit();
    };

    fill(0, 0);
    fill(1, 1);
    fill(2, 2);

    float h[4] = {0.f, 0.f, 0.f, 0.f};
    const int s0 = (w == 0) ? 4 * tid : 104 + 4 * tid;
    const bool owner =
        (w == 0) ? (tid < 28) : (tid >= 2 && tid < 30);

    for (int tg = 0; tg < NGRP; tg++) {
        int st = tg % NS;
        cpa_waitN();
        __syncthreads();  // bar1: stage ready + prior-group exchange visible

        // Halo refresh from the other warp's owned values.
        if (w == 0) {
            if (tid >= 28 && tid < 30) {
#pragma unroll
                for (int k = 0; k < 4; k++) h[k] = xb[8 + (tid - 28) * 4 + k];
            }
        } else {
            if (tid < 2) {
#pragma unroll
                for (int k = 0; k < 4; k++) h[k] = xb[tid * 4 + k];
            }
        }

        // Consume stage into registers (LDS.128 only).
        float4 q[4][4];
        char* stp = sb + st * STAGEB;
        if (HOR) {
#pragma unroll
            for (int a = 0; a < 4; a++)
#pragma unroll
                for (int k = 0; k < 4; k++)
                    q[a][k] = *(const float4*)(stp +
                                               swz((uint32_t)(a * ABYTES +
                                                              (s0 + k) * 16)));
        } else {
#pragma unroll
            for (int a = 0; a < 4; a++)
#pragma unroll
                for (int j = 0; j < 4; j++)
                    q[a][j] = *(const float4*)(stp + a * ABYTES + j * 896 +
                                               s0 * 4);
        }
        __syncthreads();  // bar2: all stage reads done -> safe to refill

        if (tg + NS < NGRP) {
            fill(st, tg + NS);
        } else {
            cpa_commit();  // keep per-thread group counts aligned
        }

        // Off-chain normalization for all 4 steps x 4 lanes.
        float A1[4][4], A2[4][4], A3[4][4], CX[4][4];
#pragma unroll
        for (int j = 0; j < 4; j++) {
#pragma unroll
            for (int k = 0; k < 4; k++) {
                float G1, G2, G3, X;
                if (HOR) {
                    int cc = REV ? 3 - j : j;  // component = step
                    G1 = ((const float*)&q[0][k])[cc];
                    G2 = ((const float*)&q[1][k])[cc];
                    G3 = ((const float*)&q[2][k])[cc];
                    X = ((const float*)&q[3][k])[cc];
                } else {  // component = lane
                    G1 = ((const float*)&q[0][j])[k];
                    G2 = ((const float*)&q[1][j])[k];
                    G3 = ((const float*)&q[2][j])[k];
                    X = ((const float*)&q[3][j])[k];
                }
                float inv = __fdividef(
                    1.0f, fmaxf(fabsf(G1) + fabsf(G2) + fabsf(G3), 1.0f));
                A1[j][k] = G1 * inv;
                A2[j][k] = G2 * inv;
                A3[j][k] = G3 * inv;
                CX[j][k] = (1.0f - A1[j][k] - A2[j][k] - A3[j][k]) * X;
            }
        }

        // Serial recurrence (4 steps).
        float hv[4][4];
#pragma unroll
        for (int j = 0; j < 4; j++) {
            float hl = __shfl_up_sync(0xffffffffu, h[3], 1);
            float hr = __shfl_down_sync(0xffffffffu, h[0], 1);
            if (w == 0 && tid == 0) hl = 0.0f;   // global left boundary
            if (w == 1 && tid == 29) hr = 0.0f;  // global right boundary

            float hn[4];
#pragma unroll
            for (int k = 0; k < 4; k++) {
                float l = (k == 0) ? hl : h[k - 1];
                float r = (k == 3) ? hr : h[k + 1];
                hn[k] = fmaf(A1[j][k], l,
                             fmaf(A2[j][k], h[k], fmaf(A3[j][k], r, CX[j][k])));
            }
#pragma unroll
            for (int k = 0; k < 4; k++) {
                h[k] = hn[k];
                hv[j][k] = hn[k];
            }
            if (!HOR && owner) {
                int row = REV ? 223 - (4 * tg + j) : 4 * tg + j;
                *(float4*)(yp + (size_t)row * WW + s0) =
                    make_float4(hn[0], hn[1], hn[2], hn[3]);
            }
        }
        if (HOR && owner) {
            int base = REV ? 220 - 4 * tg : 4 * tg;
#pragma unroll
            for (int k = 0; k < 4; k++) {
                float4 o;
                if (REV) {
                    o.x = hv[3][k]; o.y = hv[2][k];
                    o.z = hv[1][k]; o.w = hv[0][k];
                } else {
                    o.x = hv[0][k]; o.y = hv[1][k];
                    o.z = hv[2][k]; o.w = hv[3][k];
                }
                *(float4*)(yp + (size_t)(s0 + k) * WW + base) = o;
            }
        }

        // Exchange: publish owned lanes adjacent to the split (104..119).
        if (w == 0) {
            if (tid == 26 || tid == 27) {  // lanes 104..111
#pragma unroll
                for (int k = 0; k < 4; k++) xb[(tid - 26) * 4 + k] = h[k];
            }
        } else {
            if (tid == 2 || tid == 3) {  // lanes 112..119
#pragma unroll
                for (int k = 0; k < 4; k++) xb[8 + (tid - 2) * 4 + k] = h[k];
            }
        }
    }
}

// ---------------------------------------------------------------------------
// Scan kernel: grid (128 planes, 4 directions), block = 64 threads (2 warps).
// d: 0=lr (W fwd), 1=rl (H rev), 2=du (H fwd), 3=ud (W rev);
// direction d uses gate channel groups 3d..3d+2 (matches reference).
// ---------------------------------------------------------------------------
__global__ void __launch_bounds__(64) scan_kernel(
    const float* __restrict__ gates) {
    extern __shared__ __align__(128) char smem[];

    int tid = threadIdx.x & 31;
    int w = threadIdx.x >> 5;
    int plane = blockIdx.x;
    int d = blockIdx.y;
    int b = plane >> 5, c = plane & 31;

    const float* g1 = gates + ((size_t)(b * 384 + (3 * d + 0) * 32 + c)) * HW;
    const float* g2 = gates + ((size_t)(b * 384 + (3 * d + 1) * 32 + c)) * HW;
    const float* g3 = gates + ((size_t)(b * 384 + (3 * d + 2) * 32 + c)) * HW;
    const float* xp = g_x + (size_t)plane * HW;
    float* yp = g_dir + (size_t)d * NTOT + (size_t)plane * HW;

    float* xb = (float*)(smem + XB_OFF);
    if (threadIdx.x < 16) xb[threadIdx.x] = 0.0f;  // visible after bar1(tg=0)

    switch (d) {
        case 0:  warp_scan2<true,  false>(g1, g2, g3, xp, yp, smem, xb, w, tid); break;
        case 1:  warp_scan2<false, true >(g1, g2, g3, xp, yp, smem, xb, w, tid); break;
        case 2:  warp_scan2<false, false>(g1, g2, g3, xp, yp, smem, xb, w, tid); break;
        default: warp_scan2<true,  true >(g1, g2, g3, xp, yp, smem, xb, w, tid); break;
    }
}

// ---------------------------------------------------------------------------
// Combine: g_x = elementwise max over the 4 direction buffers (float4).
// ---------------------------------------------------------------------------
__global__ void combine_kernel() {
    const size_t n4 = NTOT / 4;
    const float4* p0 = (const float4*)g_dir;
    const float4* p1 = (const float4*)(g_dir + NTOT);
    const float4* p2 = (const float4*)(g_dir + 2 * NTOT);
    const float4* p3 = (const float4*)(g_dir + 3 * NTOT);
    float4* o = (float4*)g_x;
    for (size_t i = blockIdx.x * (size_t)blockDim.x + threadIdx.x; i < n4;
         i += (size_t)gridDim.x * blockDim.x) {
        float4 a = __ldg(p0 + i), b = __ldg(p1 + i);
        float4 c = __ldg(p2 + i), d = __ldg(p3 + i);
        float4 r;
        r.x = fmaxf(fmaxf(a.x, b.x), fmaxf(c.x, d.x));
        r.y = fmaxf(fmaxf(a.y, b.y), fmaxf(c.y, d.y));
        r.z = fmaxf(fmaxf(a.z, b.z), fmaxf(c.z, d.z));
        r.w = fmaxf(fmaxf(a.w, b.w), fmaxf(c.w, d.w));
        o[i] = r;
    }
}

// ---------------------------------------------------------------------------
// K3: conv2d 3x3 same 32 -> 2 on g_x, fused log_softmax over the 2 channels.
// ---------------------------------------------------------------------------
__global__ void conv_out_kernel(const float* __restrict__ w4,
                                float* __restrict__ out) {
    __shared__ float ws[576];
    for (int i = threadIdx.x; i < 576; i += blockDim.x) ws[i] = w4[i];
    __syncthreads();

    int idx = blockIdx.x * blockDim.x + threadIdx.x;
    if (idx >= BB * HW) return;
    int b = idx / HW, pix = idx - b * HW;
    int py = pix / WW, px = pix - py * WW;

    float a0 = 0.0f, a1 = 0.0f;
    for (int ic = 0; ic < 32; ic++) {
        const float* ip = g_x + ((size_t)(b * 32 + ic)) * HW;
#pragma unroll
        for (int ky = 0; ky < 3; ky++) {
            int yy = py + ky - 1;
            bool vy = (unsigned)yy < HH;
#pragma unroll
            for (int kx = 0; kx < 3; kx++) {
                int xx = px + kx - 1;
                float v = (vy && (unsigned)xx < WW)
                              ? __ldg(ip + yy * WW + xx)
                              : 0.0f;
                int wi = ic * 9 + ky * 3 + kx;
                a0 += v * ws[wi];
                a1 += v * ws[288 + wi];
            }
        }
    }
    float m = fmaxf(a0, a1);
    float l = m + logf(expf(a0 - m) + expf(a1 - m));
    out[(size_t)(b * 2) * HW + pix] = a0 - l;
    out[(size_t)(b * 2 + 1) * HW + pix] = a1 - l;
}

// ---------------------------------------------------------------------------
// Launch: K0 -> scan(pass1) -> combine -> scan(pass2) -> combine -> K3
// ---------------------------------------------------------------------------
extern "C" void kernel_launch(void* const* d_in, const int* in_sizes, int n_in,
                              void* d_out, int out_size) {
    const float* gates = (const float*)d_in[0];
    const float* y     = (const float*)d_in[1];
    const float* w3    = (const float*)d_in[2];
    const float* w4    = (const float*)d_in[3];
    float* out = (float*)d_out;

    cudaFuncSetAttribute(scan_kernel,
                         cudaFuncAttributeMaxDynamicSharedMemorySize,
                         SMEM_BYTES);

    int pxblocks = (BB * HW + 255) / 256;
    dim3 sg(NPLANE, 4);

    conv_in_kernel<<<pxblocks, 256>>>(y, w3);
    scan_kernel<<<sg, 64, SMEM_BYTES>>>(gates);
    combine_kernel<<<2048, 256>>>();
    scan_kernel<<<sg, 64, SMEM_BYTES>>>(gates);
    combine_kernel<<<2048, 256>>>();
    conv_out_kernel<<<pxblocks, 256>>>(w4, out);
}